// round 4
// baseline (speedup 1.0000x reference)
#include <cuda_runtime.h>
#include <cstdint>

#define T_LEN 2048
#define B_SZ  256
#define IN_DIM 182
#define H_DIM  64
#define G3     192   // 3*H

typedef unsigned long long ull;

// ~403 MB scratch for the input-projection output IG[B*T, 192]
__device__ float g_ig[(size_t)B_SZ * T_LEN * G3];

// ---- packed f32x2 helpers (Blackwell FFMA2 path, full fp32 precision) ----
__device__ __forceinline__ void ffma2(ull& acc, ull a, ull b) {
    asm("fma.rn.f32x2 %0, %1, %2, %0;" : "+l"(acc) : "l"(a), "l"(b));
}
__device__ __forceinline__ ull fadd2(ull a, ull b) {
    ull d; asm("add.rn.f32x2 %0, %1, %2;" : "=l"(d) : "l"(a), "l"(b)); return d;
}
__device__ __forceinline__ void unpack2(float& lo, float& hi, ull v) {
    asm("mov.b64 {%0, %1}, %2;" : "=f"(lo), "=f"(hi) : "l"(v));
}

// ---------------------------------------------------------------------------
// Kernel A: IG = X(BT x 182) @ W_ih^T(182 x 192) + bias
// BM=64, BN=192, BK=16, 256 threads, per-thread tile 4x12 (as 4x6 f32x2 pairs).
// A smem tile stored DUPLICATED so splat pairs come straight from LDS.128.
// ---------------------------------------------------------------------------
__global__ __launch_bounds__(256) void ig_gemm(const float* __restrict__ X,
                                               const float* __restrict__ Wih,
                                               const float* __restrict__ bias)
{
    __shared__ float As2[16][132];   // [k][2m] duplicated: (a,a) pairs
    __shared__ float Bs[16][196];    // [k][n]

    const int tid = threadIdx.x;
    const int mBase = blockIdx.x * 64;
    const int mg = tid >> 4;   // 0..15 : compute row group (4 rows)
    const int ng = tid & 15;   // 0..15 : compute col group (12 cols = 6 pairs)
    const int lm = tid >> 4;   // loader group
    const int lk = tid & 15;   // loader k within tile

    ull acc2[4][6];
#pragma unroll
    for (int i = 0; i < 4; i++)
#pragma unroll
        for (int j = 0; j < 6; j++) acc2[i][j] = 0ull;

    const int NT = (IN_DIM + 15) / 16;   // 12 k-tiles

    float aReg[4], bReg[12];
#pragma unroll
    for (int i = 0; i < 4; i++) {
        int k = lk;
        aReg[i] = (k < IN_DIM) ? X[(size_t)(mBase + lm + i * 16) * IN_DIM + k] : 0.f;
    }
#pragma unroll
    for (int i = 0; i < 12; i++) {
        int k = lk;
        bReg[i] = (k < IN_DIM) ? Wih[(size_t)(lm + i * 16) * IN_DIM + k] : 0.f;
    }

    for (int t = 0; t < NT; t++) {
#pragma unroll
        for (int i = 0; i < 4; i++) {
            int m2 = (lm + i * 16) * 2;
            As2[lk][m2] = aReg[i];
            As2[lk][m2 + 1] = aReg[i];
        }
#pragma unroll
        for (int i = 0; i < 12; i++) Bs[lk][lm + i * 16] = bReg[i];
        __syncthreads();

        if (t + 1 < NT) {
            const int k0n = (t + 1) * 16;
#pragma unroll
            for (int i = 0; i < 4; i++) {
                int k = k0n + lk;
                aReg[i] = (k < IN_DIM) ? X[(size_t)(mBase + lm + i * 16) * IN_DIM + k] : 0.f;
            }
#pragma unroll
            for (int i = 0; i < 12; i++) {
                int k = k0n + lk;
                bReg[i] = (k < IN_DIM) ? Wih[(size_t)(lm + i * 16) * IN_DIM + k] : 0.f;
            }
        }

#pragma unroll
        for (int k = 0; k < 16; k++) {
            // splat pairs (a0,a0),(a1,a1),(a2,a2),(a3,a3) via two LDS.128
            ulonglong2 aP0 = *(const ulonglong2*)&As2[k][mg * 8];
            ulonglong2 aP1 = *(const ulonglong2*)&As2[k][mg * 8 + 4];
            // b pairs (b0,b1)..(b10,b11) via three LDS.128
            ulonglong2 bP0 = *(const ulonglong2*)&Bs[k][ng * 12];
            ulonglong2 bP1 = *(const ulonglong2*)&Bs[k][ng * 12 + 4];
            ulonglong2 bP2 = *(const ulonglong2*)&Bs[k][ng * 12 + 8];
            ull aP[4] = {aP0.x, aP0.y, aP1.x, aP1.y};
            ull bP[6] = {bP0.x, bP0.y, bP1.x, bP1.y, bP2.x, bP2.y};
#pragma unroll
            for (int i = 0; i < 4; i++)
#pragma unroll
                for (int j = 0; j < 6; j++)
                    ffma2(acc2[i][j], aP[i], bP[j]);
        }
        __syncthreads();
    }

    // epilogue: add bias (packed), store pairs
    ull bp[6];
#pragma unroll
    for (int j = 0; j < 6; j++) bp[j] = *(const ull*)&bias[ng * 12 + 2 * j];
#pragma unroll
    for (int i = 0; i < 4; i++) {
        size_t row = (size_t)(mBase + mg * 4 + i);
        ull* o = (ull*)&g_ig[row * G3 + ng * 12];
#pragma unroll
        for (int j = 0; j < 6; j++) o[j] = fadd2(acc2[i][j], bp[j]);
    }
}

// ---------------------------------------------------------------------------
// Kernel B: GRU scan. One CTA per batch element, 192 threads.
// Thread j owns gate-row j of W_hh as 32 packed f32x2 pairs.
// ---------------------------------------------------------------------------
__device__ __forceinline__ float fsigmoid(float x) {
    return __fdividef(1.f, 1.f + __expf(-x));
}
__device__ __forceinline__ float ftanh(float x) {
    return __fdividef(2.f, 1.f + __expf(-2.f * x)) - 1.f;
}

__global__ __launch_bounds__(192) void gru_scan(const float* __restrict__ whh,      // [192,64]
                                                const float* __restrict__ bias_n,   // [64]
                                                const float* __restrict__ wout,     // [2,64]
                                                const float* __restrict__ out_bias, // [2]
                                                float* __restrict__ out)            // [B,2]
{
    const int b = blockIdx.x;
    const int j = threadIdx.x;           // 0..191

    __shared__ float sh_h[64];
    __shared__ float sh_pre[192];        // j<128: ig+hg ; j>=128: ig_n
    __shared__ float sh_b[64];           // hg_n + bias_n

    // W_hh row j as 32 packed pairs (64 regs)
    ull wp[32];
#pragma unroll
    for (int q = 0; q < 32; q++) wp[q] = *(const ull*)&whh[j * 64 + 2 * q];

    const float bn = (j >= 128) ? bias_n[j - 128] : 0.f;

    if (j < 64) sh_h[j] = 0.f;

    const float* igp = g_ig + (size_t)b * T_LEN * G3 + j;
    float ig_next = igp[0];
    __syncthreads();

    for (int t = 0; t < T_LEN; t++) {
        const float igc = ig_next;
        if (t < T_LEN - 1) ig_next = igp[(size_t)(t + 1) * G3];

        // hg_j = dot(W_hh[j,:], h) with packed pairs, 4 independent chains
        ull a0 = 0ull, a1 = 0ull, a2 = 0ull, a3 = 0ull;
#pragma unroll
        for (int q = 0; q < 32; q += 4) {
            ulonglong2 h01 = *(const ulonglong2*)&sh_h[2 * q];      // pairs q, q+1
            ulonglong2 h23 = *(const ulonglong2*)&sh_h[2 * q + 4];  // pairs q+2, q+3
            ffma2(a0, wp[q],     h01.x);
            ffma2(a1, wp[q + 1], h01.y);
            ffma2(a2, wp[q + 2], h23.x);
            ffma2(a3, wp[q + 3], h23.y);
        }
        float s0, s1, s2, s3, s4, s5, s6, s7;
        unpack2(s0, s1, a0); unpack2(s2, s3, a1);
        unpack2(s4, s5, a2); unpack2(s6, s7, a3);
        const float hg = ((s0 + s1) + (s2 + s3)) + ((s4 + s5) + (s6 + s7));

        if (j < 128) {
            sh_pre[j] = igc + hg;
        } else {
            sh_pre[j] = igc;
            sh_b[j - 128] = hg + bn;
        }
        __syncthreads();

        if (j < 64) {
            const float r = fsigmoid(sh_pre[j]);
            const float z = fsigmoid(sh_pre[64 + j]);
            const float n = ftanh(sh_pre[128 + j] + r * sh_b[j]);
            const float h = sh_h[j];
            sh_h[j] = n + z * (h - n);
        }
        __syncthreads();
    }

    // readout: OUT=2
    if (j < 2) {
        float acc = 0.f;
#pragma unroll 8
        for (int k = 0; k < 64; k++) acc += wout[j * 64 + k] * sh_h[k];
        out[b * 2 + j] = fsigmoid(acc + out_bias[j]);
    }
}

// ---------------------------------------------------------------------------
extern "C" void kernel_launch(void* const* d_in, const int* in_sizes, int n_in,
                              void* d_out, int out_size)
{
    const float* x        = (const float*)d_in[0];   // (256,2048,182)
    const float* wih      = (const float*)d_in[1];   // (192,182)
    const float* whh      = (const float*)d_in[2];   // (192,64)
    const float* bias     = (const float*)d_in[3];   // (192,)
    const float* bias_n   = (const float*)d_in[4];   // (64,)
    const float* wout     = (const float*)d_in[5];   // (2,64)
    const float* out_bias = (const float*)d_in[6];   // (2,)
    float* out = (float*)d_out;                      // (256,2)

    const int BT = B_SZ * T_LEN;
    ig_gemm<<<BT / 64, 256>>>(x, wih, bias);
    gru_scan<<<B_SZ, 192>>>(whh, bias_n, wout, out_bias, out);
}

// round 7
// speedup vs baseline: 1.6633x; 1.6633x over previous
#include <cuda_runtime.h>
#include <cstdint>

#define T_LEN 2048
#define B_SZ  256
#define IN_DIM 182
#define G3     192
#define KC     32
#define NCHUNK 6
#define M_TILE 128

typedef unsigned long long ull;

// scratch: IG[B*T,192] (~403MB) + pair-interleaved split-B images [chunk][192][32]
__device__ float g_ig[(size_t)B_SZ * T_LEN * G3];
__device__ __align__(16) float g_bh[NCHUNK * G3 * KC];
__device__ __align__(16) float g_bl[NCHUNK * G3 * KC];

// ---------------- helpers ----------------
__device__ __forceinline__ uint32_t smem_u32(const void* p) {
    uint32_t a;
    asm("{ .reg .u64 t; cvta.to.shared.u64 t, %1; cvt.u32.u64 %0, t; }" : "=r"(a) : "l"(p));
    return a;
}
__device__ __forceinline__ void cp_async16(uint32_t dst, const void* src) {
    asm volatile("cp.async.cg.shared.global [%0], [%1], 16;" :: "r"(dst), "l"(src) : "memory");
}
__device__ __forceinline__ void cp_async8(uint32_t dst, const void* src) {
    asm volatile("cp.async.ca.shared.global [%0], [%1], 8;" :: "r"(dst), "l"(src) : "memory");
}
#define CP_COMMIT() asm volatile("cp.async.commit_group;" ::: "memory")
#define CP_WAIT0()  asm volatile("cp.async.wait_group 0;" ::: "memory")

// m16n8k8 tf32 MMA: D(f32) += A(tf32-bits) * B(tf32-bits)
__device__ __forceinline__ void mma8(float* d, const uint32_t* a, uint32_t b0, uint32_t b1) {
    asm volatile("mma.sync.aligned.m16n8k8.row.col.f32.tf32.tf32.f32 "
                 "{%0,%1,%2,%3}, {%4,%5,%6,%7}, {%8,%9}, {%0,%1,%2,%3};"
                 : "+f"(d[0]), "+f"(d[1]), "+f"(d[2]), "+f"(d[3])
                 : "r"(a[0]), "r"(a[1]), "r"(a[2]), "r"(a[3]), "r"(b0), "r"(b1));
}

// ---------------------------------------------------------------------------
// prep_b: split W_ih (+bias as K-col 182) into tf32-exact hi + f32 lo.
// Stored [chunk][n=192][32] with PAIR-INTERLEAVED k order inside each k8 group:
//   local col lc: ks=lc>>3, p=(lc&7)>>1, e=lc&1  ->  k = c*32 + ks*8 + p + 4e
// so {B[n][k], B[n][k+4]} are adjacent (one LDS.64 per fragment).
// ---------------------------------------------------------------------------
__global__ void prep_b(const float* __restrict__ wih, const float* __restrict__ bias)
{
    int idx = blockIdx.x * 256 + threadIdx.x;      // 6*192*32 = 36864
    if (idx >= NCHUNK * G3 * KC) return;
    int c   = idx / (G3 * KC);
    int rem = idx % (G3 * KC);
    int n   = rem / KC;
    int lc  = rem % KC;
    int ks = lc >> 3, p = (lc & 7) >> 1, e = lc & 1;
    int k = c * KC + ks * 8 + p + 4 * e;
    float w = (k < IN_DIM) ? wih[n * IN_DIM + k] : ((k == IN_DIM) ? bias[n] : 0.f);
    float hi = __uint_as_float(__float_as_uint(w) & 0xFFFFE000u);   // exact tf32
    g_bh[idx] = hi;
    g_bl[idx] = w - hi;
}

// ---------------------------------------------------------------------------
// ig_mma: IG = X @ W^T via mma.sync tf32 (2-term split).
// CTA: 128 rows x 192 cols, 8 warps; warp tile 32(M) x 96(N).
// smem: A[128][40] raw f32 | Bh[192][40] | Bl[192][40]  (stride 40 = bank-safe)
// A staged with 8B cp.async (X rows are only 8B-aligned: 182*4 mod 16 = 8).
// ---------------------------------------------------------------------------
#define A_STRIDE 40
#define SMO_A   0u
#define SMO_BH  20480u
#define SMO_BL  51200u
#define SM_TOT  81920u

__global__ __launch_bounds__(256, 2) void ig_mma(const float* __restrict__ X)
{
    extern __shared__ __align__(16) float smem[];
    float* As = smem;                        // [128][40]
    float* Bh = smem + SMO_BH / 4;           // [192][40]
    float* Bl = smem + SMO_BL / 4;
    const uint32_t sb = smem_u32(smem);

    const int tid  = threadIdx.x;
    const int wid  = tid >> 5;
    const int lane = tid & 31;
    const int mBase = blockIdx.x * M_TILE;

    const int wm = (wid & 3) * 32;           // warp M offset
    const int wn = (wid >> 2) * 96;          // warp N offset
    const int lr = lane >> 2;                // 0..7
    const int lc = lane & 3;                 // 0..3

    float acc[2][12][4];
#pragma unroll
    for (int mf = 0; mf < 2; mf++)
#pragma unroll
        for (int nt = 0; nt < 12; nt++)
#pragma unroll
            for (int q = 0; q < 4; q++) acc[mf][nt][q] = 0.f;

    // A staging geometry: row = tid>>1, half = tid&1 (16 cols each)
    const int row  = tid >> 1;
    const int half = tid & 1;
    const float* xrow = X + (size_t)(mBase + row) * IN_DIM;

    for (int c = 0; c < NCHUNK; c++) {
        // ---- stage B (hi+lo): 6 x 16B per term per thread ----
        const float* srcH = g_bh + (size_t)c * G3 * KC;
        const float* srcL = g_bl + (size_t)c * G3 * KC;
#pragma unroll
        for (int j = 0; j < 6; j++) {
            int id = tid + j * 256;          // 0..1535
            int n  = id >> 3;
            int q4 = (id & 7) * 4;
            uint32_t doff = (uint32_t)(n * A_STRIDE + q4) * 4u;
            cp_async16(sb + SMO_BH + doff, srcH + n * KC + q4);
            cp_async16(sb + SMO_BL + doff, srcL + n * KC + q4);
        }
        // ---- stage A: 8 x 8B per thread (X rows are 8B-aligned) ----
        const int kb = c * KC + half * 16;
        const uint32_t aBase = sb + SMO_A + (uint32_t)(row * A_STRIDE + half * 16) * 4u;
#pragma unroll
        for (int i = 0; i < 8; i++) {
            int kk = kb + 2 * i;
            if (kk + 1 < IN_DIM)
                cp_async8(aBase + (uint32_t)(8 * i), xrow + kk);
        }
        if (c == NCHUNK - 1 && half == 1) {
            // tail k=182..191: bias column =1.0 @ local col 22, zeros after
            float* ar = As + row * A_STRIDE;
            ar[22] = 1.0f;
#pragma unroll
            for (int i = 23; i < 32; i++) ar[i] = 0.f;
        }
        CP_COMMIT();
        CP_WAIT0();
        __syncthreads();

        // ---- compute: 4 k8-steps ----
#pragma unroll
        for (int ks = 0; ks < 4; ks++) {
            uint32_t a[2][4];
#pragma unroll
            for (int mf = 0; mf < 2; mf++) {
                const float* ar  = As + (wm + mf * 16 + lr) * A_STRIDE + ks * 8 + lc;
                const float* ar8 = ar + 8 * A_STRIDE;
                a[mf][0] = __float_as_uint(ar[0]);
                a[mf][1] = __float_as_uint(ar8[0]);
                a[mf][2] = __float_as_uint(ar[4]);
                a[mf][3] = __float_as_uint(ar8[4]);
            }
#pragma unroll
            for (int nt = 0; nt < 12; nt++) {
                int boff = (wn + nt * 8 + lr) * A_STRIDE + ks * 8 + 2 * lc;
                uint2 bh = *(const uint2*)(Bh + boff);
                uint2 bl = *(const uint2*)(Bl + boff);
                mma8(acc[0][nt], a[0], bh.x, bh.y);
                mma8(acc[1][nt], a[1], bh.x, bh.y);
                mma8(acc[0][nt], a[0], bl.x, bl.y);
                mma8(acc[1][nt], a[1], bl.x, bl.y);
            }
        }
        __syncthreads();
    }

    // ---- epilogue: c0,c1 @ (r, col), c2,c3 @ (r+8, col) ----
#pragma unroll
    for (int mf = 0; mf < 2; mf++) {
        const int r0 = mBase + wm + mf * 16 + lr;
#pragma unroll
        for (int nt = 0; nt < 12; nt++) {
            const int col = wn + nt * 8 + 2 * lc;
            *(float2*)&g_ig[(size_t)r0 * G3 + col] =
                make_float2(acc[mf][nt][0], acc[mf][nt][1]);
            *(float2*)&g_ig[(size_t)(r0 + 8) * G3 + col] =
                make_float2(acc[mf][nt][2], acc[mf][nt][3]);
        }
    }
}

// ---------------------------------------------------------------------------
// GRU scan: one CTA/batch, 192 threads, FFMA2 dots, 4-deep ig prefetch ring.
// ---------------------------------------------------------------------------
__device__ __forceinline__ void ffma2(ull& acc, ull a, ull b) {
    asm("fma.rn.f32x2 %0, %1, %2, %0;" : "+l"(acc) : "l"(a), "l"(b));
}
__device__ __forceinline__ void unpack2(float& lo, float& hi, ull v) {
    asm("mov.b64 {%0, %1}, %2;" : "=f"(lo), "=f"(hi) : "l"(v));
}
__device__ __forceinline__ float fsigmoid(float x) { return __fdividef(1.f, 1.f + __expf(-x)); }
__device__ __forceinline__ float ftanh(float x)    { return __fdividef(2.f, 1.f + __expf(-2.f * x)) - 1.f; }

__global__ __launch_bounds__(192) void gru_scan(const float* __restrict__ whh,
                                                const float* __restrict__ bias_n,
                                                const float* __restrict__ wout,
                                                const float* __restrict__ out_bias,
                                                float* __restrict__ out)
{
    const int b = blockIdx.x;
    const int j = threadIdx.x;

    __shared__ float sh_h[64];
    __shared__ float sh_pre[192];
    __shared__ float sh_b[64];

    ull wp[32];
#pragma unroll
    for (int q = 0; q < 32; q++) wp[q] = *(const ull*)&whh[j * 64 + 2 * q];

    const float bn = (j >= 128) ? bias_n[j - 128] : 0.f;
    if (j < 64) sh_h[j] = 0.f;

    const float* igp = g_ig + (size_t)b * T_LEN * G3 + j;
    float ign[4];
#pragma unroll
    for (int u = 0; u < 4; u++) ign[u] = igp[(size_t)u * G3];
    __syncthreads();

    for (int t = 0; t < T_LEN; t += 4) {
#pragma unroll
        for (int u = 0; u < 4; u++) {
            const float igc = ign[u];
            const int tn = t + 4 + u;
            if (tn < T_LEN) ign[u] = igp[(size_t)tn * G3];

            ull a0 = 0ull, a1 = 0ull, a2 = 0ull, a3 = 0ull;
#pragma unroll
            for (int q = 0; q < 32; q += 4) {
                ulonglong2 h01 = *(const ulonglong2*)&sh_h[2 * q];
                ulonglong2 h23 = *(const ulonglong2*)&sh_h[2 * q + 4];
                ffma2(a0, wp[q],     h01.x);
                ffma2(a1, wp[q + 1], h01.y);
                ffma2(a2, wp[q + 2], h23.x);
                ffma2(a3, wp[q + 3], h23.y);
            }
            float s0, s1, s2, s3, s4, s5, s6, s7;
            unpack2(s0, s1, a0); unpack2(s2, s3, a1);
            unpack2(s4, s5, a2); unpack2(s6, s7, a3);
            const float hg = ((s0 + s1) + (s2 + s3)) + ((s4 + s5) + (s6 + s7));

            if (j < 128) {
                sh_pre[j] = igc + hg;
            } else {
                sh_pre[j] = igc;
                sh_b[j - 128] = hg + bn;
            }
            __syncthreads();

            if (j < 64) {
                const float r = fsigmoid(sh_pre[j]);
                const float z = fsigmoid(sh_pre[64 + j]);
                const float n = ftanh(sh_pre[128 + j] + r * sh_b[j]);
                const float h = sh_h[j];
                sh_h[j] = n + z * (h - n);
            }
            __syncthreads();
        }
    }

    if (j < 2) {
        float acc = 0.f;
#pragma unroll 8
        for (int k = 0; k < 64; k++) acc += wout[j * 64 + k] * sh_h[k];
        out[b * 2 + j] = fsigmoid(acc + out_bias[j]);
    }
}

// ---------------------------------------------------------------------------
extern "C" void kernel_launch(void* const* d_in, const int* in_sizes, int n_in,
                              void* d_out, int out_size)
{
    const float* x        = (const float*)d_in[0];
    const float* wih      = (const float*)d_in[1];
    const float* whh      = (const float*)d_in[2];
    const float* bias     = (const float*)d_in[3];
    const float* bias_n   = (const float*)d_in[4];
    const float* wout     = (const float*)d_in[5];
    const float* out_bias = (const float*)d_in[6];
    float* out = (float*)d_out;

    cudaFuncSetAttribute(ig_mma, cudaFuncAttributeMaxDynamicSharedMemorySize, SM_TOT);

    prep_b<<<(NCHUNK * G3 * KC + 255) / 256, 256>>>(wih, bias);
    ig_mma<<<(B_SZ * T_LEN) / M_TILE, 256, SM_TOT>>>(x);
    gru_scan<<<B_SZ, 192>>>(whh, bias_n, wout, out_bias, out);
}

// round 8
// speedup vs baseline: 1.8118x; 1.0893x over previous
#include <cuda_runtime.h>
#include <cstdint>

#define T_LEN 2048
#define B_SZ  256
#define IN_DIM 182
#define G3     192
#define KC     32
#define NCHUNK 6
#define M_TILE 128

typedef unsigned long long ull;

// scratch: IG[B*T,192] (~403MB) + pair-interleaved split-B images [chunk][192][32]
__device__ float g_ig[(size_t)B_SZ * T_LEN * G3];
__device__ __align__(16) float g_bh[NCHUNK * G3 * KC];
__device__ __align__(16) float g_bl[NCHUNK * G3 * KC];

// ---------------- helpers ----------------
__device__ __forceinline__ uint32_t smem_u32(const void* p) {
    uint32_t a;
    asm("{ .reg .u64 t; cvta.to.shared.u64 t, %1; cvt.u32.u64 %0, t; }" : "=r"(a) : "l"(p));
    return a;
}
__device__ __forceinline__ void cp_async16(uint32_t dst, const void* src) {
    asm volatile("cp.async.cg.shared.global [%0], [%1], 16;" :: "r"(dst), "l"(src) : "memory");
}
__device__ __forceinline__ void cp_async8(uint32_t dst, const void* src) {
    asm volatile("cp.async.ca.shared.global [%0], [%1], 8;" :: "r"(dst), "l"(src) : "memory");
}
#define CP_COMMIT() asm volatile("cp.async.commit_group;" ::: "memory")
#define CP_WAIT0()  asm volatile("cp.async.wait_group 0;" ::: "memory")

// m16n8k8 tf32 MMA
__device__ __forceinline__ void mma8(float* d, const uint32_t* a, uint32_t b0, uint32_t b1) {
    asm volatile("mma.sync.aligned.m16n8k8.row.col.f32.tf32.tf32.f32 "
                 "{%0,%1,%2,%3}, {%4,%5,%6,%7}, {%8,%9}, {%0,%1,%2,%3};"
                 : "+f"(d[0]), "+f"(d[1]), "+f"(d[2]), "+f"(d[3])
                 : "r"(a[0]), "r"(a[1]), "r"(a[2]), "r"(a[3]), "r"(b0), "r"(b1));
}

__device__ __forceinline__ void ffma2(ull& acc, ull a, ull b) {
    asm("fma.rn.f32x2 %0, %1, %2, %0;" : "+l"(acc) : "l"(a), "l"(b));
}
__device__ __forceinline__ void unpack2(float& lo, float& hi, ull v) {
    asm("mov.b64 {%0, %1}, %2;" : "=f"(lo), "=f"(hi) : "l"(v));
}
__device__ __forceinline__ float fsigmoid(float x) { return __fdividef(1.f, 1.f + __expf(-x)); }
__device__ __forceinline__ float ftanh(float x)    { return __fdividef(2.f, 1.f + __expf(-2.f * x)) - 1.f; }

// ---------------------------------------------------------------------------
// prep_b: split W_ih (+bias as K-col 182) into tf32-exact hi + f32 lo.
// Pair-interleaved k inside each k8 group: lc -> k = c*32 + (lc>>3)*8 + ((lc&7)>>1) + 4*(lc&1)
// ---------------------------------------------------------------------------
__global__ void prep_b(const float* __restrict__ wih, const float* __restrict__ bias)
{
    int idx = blockIdx.x * 256 + threadIdx.x;      // 36864
    if (idx >= NCHUNK * G3 * KC) return;
    int c   = idx / (G3 * KC);
    int rem = idx % (G3 * KC);
    int n   = rem / KC;
    int lc  = rem % KC;
    int ks = lc >> 3, p = (lc & 7) >> 1, e = lc & 1;
    int k = c * KC + ks * 8 + p + 4 * e;
    float w = (k < IN_DIM) ? wih[n * IN_DIM + k] : ((k == IN_DIM) ? bias[n] : 0.f);
    float hi = __uint_as_float(__float_as_uint(w) & 0xFFFFE000u);
    g_bh[idx] = hi;
    g_bl[idx] = w - hi;
}

// ---------------------------------------------------------------------------
// ig_mma: IG = X @ W^T via mma.sync tf32 (2-term split), 2-stage pipeline.
// smem: A0[128][40] | A1[128][40] | Bh[192][40] | Bl[192][40]  -> 100KB, occ=2
// ---------------------------------------------------------------------------
#define A_STRIDE 40
#define SMO_A0  0u
#define SMO_A1  20480u
#define SMO_BH  40960u
#define SMO_BL  71680u
#define SM_TOT  102400u

__global__ __launch_bounds__(256, 2) void ig_mma(const float* __restrict__ X)
{
    extern __shared__ __align__(16) float smem[];
    float* Bh = smem + SMO_BH / 4;
    float* Bl = smem + SMO_BL / 4;
    const uint32_t sb = smem_u32(smem);

    const int tid  = threadIdx.x;
    const int wid  = tid >> 5;
    const int lane = tid & 31;
    const int mBase = blockIdx.x * M_TILE;

    const int wm = (wid & 3) * 32;
    const int wn = (wid >> 2) * 96;
    const int lr = lane >> 2;
    const int lc = lane & 3;

    float acc[2][12][4];
#pragma unroll
    for (int mf = 0; mf < 2; mf++)
#pragma unroll
        for (int nt = 0; nt < 12; nt++)
#pragma unroll
            for (int q = 0; q < 4; q++) acc[mf][nt][q] = 0.f;

    const int row  = tid >> 1;
    const int half = tid & 1;
    const float* xrow = X + (size_t)(mBase + row) * IN_DIM;
    const uint32_t aRowOff = (uint32_t)(row * A_STRIDE + half * 16) * 4u;

    // ---- stage A(chunk) into given buffer (8B cp.async; X rows 8B-aligned) ----
    auto stageA = [&](int c, uint32_t smoA) {
        const int kb = c * KC + half * 16;
        const uint32_t aBase = sb + smoA + aRowOff;
#pragma unroll
        for (int i = 0; i < 8; i++) {
            int kk = kb + 2 * i;
            if (kk + 1 < IN_DIM) cp_async8(aBase + (uint32_t)(8 * i), xrow + kk);
        }
        if (c == NCHUNK - 1 && half == 1) {
            float* ar = (float*)(smem + smoA / 4) + row * A_STRIDE;
            ar[22] = 1.0f;                       // bias column k=182
#pragma unroll
            for (int i = 23; i < 32; i++) ar[i] = 0.f;
        }
    };
    // ---- stage B(chunk) ----
    auto stageB = [&](int c) {
        const float* srcH = g_bh + (size_t)c * G3 * KC;
        const float* srcL = g_bl + (size_t)c * G3 * KC;
#pragma unroll
        for (int j = 0; j < 6; j++) {
            int id = tid + j * 256;
            int n  = id >> 3;
            int q4 = (id & 7) * 4;
            uint32_t doff = (uint32_t)(n * A_STRIDE + q4) * 4u;
            cp_async16(sb + SMO_BH + doff, srcH + n * KC + q4);
            cp_async16(sb + SMO_BL + doff, srcL + n * KC + q4);
        }
    };

    // prologue
    stageA(0, SMO_A0);
    stageB(0);
    CP_COMMIT(); CP_WAIT0();
    __syncthreads();

    for (int c = 0; c < NCHUNK; c++) {
        // prefetch A(c+1) into the other buffer (overlaps with compute)
        if (c + 1 < NCHUNK) {
            stageA(c + 1, ((c + 1) & 1) ? SMO_A1 : SMO_A0);
            CP_COMMIT();
        }
        const float* As = smem + ((c & 1) ? SMO_A1 : SMO_A0) / 4;

        // ---- compute: 4 k8-steps ----
#pragma unroll
        for (int ks = 0; ks < 4; ks++) {
            uint32_t a[2][4];
#pragma unroll
            for (int mf = 0; mf < 2; mf++) {
                const float* ar  = As + (wm + mf * 16 + lr) * A_STRIDE + ks * 8 + lc;
                const float* ar8 = ar + 8 * A_STRIDE;
                a[mf][0] = __float_as_uint(ar[0]);
                a[mf][1] = __float_as_uint(ar8[0]);
                a[mf][2] = __float_as_uint(ar[4]);
                a[mf][3] = __float_as_uint(ar8[4]);
            }
#pragma unroll
            for (int nt = 0; nt < 12; nt++) {
                int boff = (wn + nt * 8 + lr) * A_STRIDE + ks * 8 + 2 * lc;
                uint2 bh = *(const uint2*)(Bh + boff);
                uint2 bl = *(const uint2*)(Bl + boff);
                mma8(acc[0][nt], a[0], bh.x, bh.y);
                mma8(acc[1][nt], a[1], bh.x, bh.y);
                mma8(acc[0][nt], a[0], bl.x, bl.y);
                mma8(acc[1][nt], a[1], bl.x, bl.y);
            }
        }
        __syncthreads();                         // all warps done reading B(c)
        if (c + 1 < NCHUNK) {
            stageB(c + 1);
            CP_COMMIT(); CP_WAIT0();             // waits B(c+1) and A(c+1)
            __syncthreads();
        }
    }

    // ---- epilogue ----
#pragma unroll
    for (int mf = 0; mf < 2; mf++) {
        const int r0 = mBase + wm + mf * 16 + lr;
#pragma unroll
        for (int nt = 0; nt < 12; nt++) {
            const int col = wn + nt * 8 + 2 * lc;
            *(float2*)&g_ig[(size_t)r0 * G3 + col] =
                make_float2(acc[mf][nt][0], acc[mf][nt][1]);
            *(float2*)&g_ig[(size_t)(r0 + 8) * G3 + col] =
                make_float2(acc[mf][nt][2], acc[mf][nt][3]);
        }
    }
}

// ---------------------------------------------------------------------------
// GRU scan: 64 threads/CTA, thread j owns gate rows j / 64+j / 128+j entirely
// (weights in registers). h double-buffered in smem -> ONE barrier per step.
// ---------------------------------------------------------------------------
__global__ __launch_bounds__(64) void gru_scan(const float* __restrict__ whh,
                                               const float* __restrict__ bias_n,
                                               const float* __restrict__ wout,
                                               const float* __restrict__ out_bias,
                                               float* __restrict__ out)
{
    const int b = blockIdx.x;
    const int j = threadIdx.x;                 // 0..63

    __shared__ float sh_h[2][64];

    ull wr[32], wz[32], wn[32];
#pragma unroll
    for (int q = 0; q < 32; q++) {
        wr[q] = *(const ull*)&whh[(j)        * 64 + 2 * q];
        wz[q] = *(const ull*)&whh[(64 + j)   * 64 + 2 * q];
        wn[q] = *(const ull*)&whh[(128 + j)  * 64 + 2 * q];
    }
    const float bn = bias_n[j];

    float hreg = 0.f;
    sh_h[0][j] = 0.f;

    const float* igp = g_ig + (size_t)b * T_LEN * G3;
    float pr[4], pz[4], pn[4];
#pragma unroll
    for (int u = 0; u < 4; u++) {
        pr[u] = igp[(size_t)u * G3 + j];
        pz[u] = igp[(size_t)u * G3 + 64 + j];
        pn[u] = igp[(size_t)u * G3 + 128 + j];
    }
    __syncthreads();

    int p = 0;
    for (int t = 0; t < T_LEN; t += 4) {
#pragma unroll
        for (int u = 0; u < 4; u++) {
            const float igr = pr[u], igz = pz[u], ign = pn[u];
            const int tn = t + 4 + u;
            if (tn < T_LEN) {
                const float* g = igp + (size_t)tn * G3;
                pr[u] = g[j];
                pz[u] = g[64 + j];
                pn[u] = g[128 + j];
            }

            // three 64-dot products against shared h
            ull ar0 = 0, ar1 = 0, az0 = 0, az1 = 0, an0 = 0, an1 = 0;
            const float* hb = sh_h[p];
#pragma unroll
            for (int q = 0; q < 32; q += 2) {
                ulonglong2 h2 = *(const ulonglong2*)&hb[2 * q];   // pairs q, q+1
                ffma2(ar0, wr[q], h2.x); ffma2(ar1, wr[q + 1], h2.y);
                ffma2(az0, wz[q], h2.x); ffma2(az1, wz[q + 1], h2.y);
                ffma2(an0, wn[q], h2.x); ffma2(an1, wn[q + 1], h2.y);
            }
            float x0, x1, y0, y1;
            unpack2(x0, x1, ar0); unpack2(y0, y1, ar1);
            const float hgr = (x0 + x1) + (y0 + y1);
            unpack2(x0, x1, az0); unpack2(y0, y1, az1);
            const float hgz = (x0 + x1) + (y0 + y1);
            unpack2(x0, x1, an0); unpack2(y0, y1, an1);
            const float hgn = (x0 + x1) + (y0 + y1);

            const float r = fsigmoid(igr + hgr);
            const float z = fsigmoid(igz + hgz);
            const float n = ftanh(ign + r * (hgn + bn));
            hreg = n + z * (hreg - n);

            sh_h[1 - p][j] = hreg;
            __syncthreads();
            p ^= 1;
        }
    }

    // readout
    sh_h[0][j] = hreg;
    __syncthreads();
    if (j < 2) {
        float acc = 0.f;
#pragma unroll 8
        for (int k = 0; k < 64; k++) acc += wout[j * 64 + k] * sh_h[0][k];
        out[b * 2 + j] = fsigmoid(acc + out_bias[j]);
    }
}

// ---------------------------------------------------------------------------
extern "C" void kernel_launch(void* const* d_in, const int* in_sizes, int n_in,
                              void* d_out, int out_size)
{
    const float* x        = (const float*)d_in[0];
    const float* wih      = (const float*)d_in[1];
    const float* whh      = (const float*)d_in[2];
    const float* bias     = (const float*)d_in[3];
    const float* bias_n   = (const float*)d_in[4];
    const float* wout     = (const float*)d_in[5];
    const float* out_bias = (const float*)d_in[6];
    float* out = (float*)d_out;

    cudaFuncSetAttribute(ig_mma, cudaFuncAttributeMaxDynamicSharedMemorySize, SM_TOT);

    prep_b<<<(NCHUNK * G3 * KC + 255) / 256, 256>>>(wih, bias);
    ig_mma<<<(B_SZ * T_LEN) / M_TILE, 256, SM_TOT>>>(x);
    gru_scan<<<B_SZ, 64>>>(whh, bias_n, wout, out_bias, out);
}